// round 4
// baseline (speedup 1.0000x reference)
#include <cuda_runtime.h>
#include <cuda_bf16.h>

typedef unsigned long long u64;

#define NOBJ 7
#define MAXB 50000
#define TWO_PI 6.283185307179586f
#define LN_SIGMA 3.2188758248682006f   /* ln(25) */

/* time-embedding xs[b][32] scratch */
__device__ float g_xs[MAXB * 32];

/* ---------------- packed fp32x2 helpers ---------------- */
__device__ __forceinline__ u64 ffma2(u64 a, u64 b, u64 c) {
    u64 d;
    asm("fma.rn.f32x2 %0, %1, %2, %3;" : "=l"(d) : "l"(a), "l"(b), "l"(c));
    return d;
}
__device__ __forceinline__ u64 add2(u64 a, u64 b) {
    u64 d;
    asm("add.rn.f32x2 %0, %1, %2;" : "=l"(d) : "l"(a), "l"(b));
    return d;
}
__device__ __forceinline__ u64 pack2(float x, float y) {
    u64 r; asm("mov.b64 %0, {%1, %2};" : "=l"(r) : "f"(x), "f"(y)); return r;
}
__device__ __forceinline__ float2 unpack2(u64 v) {
    float x, y; asm("mov.b64 {%0, %1}, %2;" : "=f"(x), "=f"(y) : "l"(v));
    return make_float2(x, y);
}
__device__ __forceinline__ u64 relu2(u64 a) {
    float2 f = unpack2(a);
    return pack2(fmaxf(f.x, 0.f), fmaxf(f.y, 0.f));
}

/* ---------------- smem layout (float offsets) ---------------- */
#define OWI1 0
#define OWI2 192
#define OW1S 4288
#define OW1N 8384
#define OW1B 12480
#define OW2S 16576
#define OW2N 22720
#define OW2B 28864
#define OW3S 32960
#define OW3N 39104
#define OW3B 45248
#define OBI1 45440
#define OBI2 45504
#define OB1A 45568
#define OB1B 45632
#define OB2A 45696
#define OB2B 45760
#define OB3A 45824
#define OB3B 45888
#define OACT 45892                 /* u64-aligned (byte 183568) */
#define WARP_ACT 672               /* u64 per warp: x 7*64, sigma 7*32 */
#define NWARP 8
#define SMEM_BYTES (OACT * 4 + NWARP * WARP_ACT * 8)   /* 226,576 B */

/* ================= kernel 1: time embedding xs ================= */
__global__ void xs_kernel(const float* __restrict__ t, const float* __restrict__ Wf,
                          const float* __restrict__ wt, const float* __restrict__ bt,
                          int Bn) {
    __shared__ float swt[1024], sbt[32], swf[16];
    for (int i = threadIdx.x; i < 1024; i += blockDim.x) swt[i] = wt[i];
    if (threadIdx.x < 32) sbt[threadIdx.x] = bt[threadIdx.x];
    if (threadIdx.x < 16) swf[threadIdx.x] = Wf[threadIdx.x];
    __syncthreads();
    int b = blockIdx.x * blockDim.x + threadIdx.x;
    if (b >= Bn) return;
    float tb = t[b];
    float r[32];
#pragma unroll
    for (int m = 0; m < 16; m++) {
        float p = tb * swf[m] * TWO_PI;
        r[m]      = fmaxf(sinf(p), 0.f);
        r[16 + m] = fmaxf(cosf(p), 0.f);
    }
    float* o = g_xs + (size_t)b * 32;
#pragma unroll 4
    for (int c = 0; c < 32; c++) {
        float a = sbt[c];
#pragma unroll
        for (int k = 0; k < 32; k++) a = fmaf(r[k], swt[k * 32 + c], a);
        o[c] = fmaxf(a, 0.f);
    }
}

/* ======= u/v phase: u[n]=x_n@WS+ba, v[n]=x_n@WN (graph-pair packed) ======= */
template <bool SIG>
__device__ __forceinline__ void uv_phase(const u64* __restrict__ xq,
                                         const u64* __restrict__ sg,
                                         const float* __restrict__ WS,
                                         const float* __restrict__ WN,
                                         const float* __restrict__ BA,
                                         int l, u64 (&u)[7][2], u64 (&v)[7][2]) {
    float2 ba = *reinterpret_cast<const float2*>(&BA[2 * l]);
#pragma unroll
    for (int n = 0; n < 7; n++) {
        u[n][0] = pack2(ba.x, ba.x); u[n][1] = pack2(ba.y, ba.y);
        v[n][0] = 0ULL;              v[n][1] = 0ULL;
    }
#pragma unroll 2
    for (int k = 0; k < 64; k++) {
        float2 ws = *reinterpret_cast<const float2*>(&WS[k * 64 + 2 * l]);
        float2 wn = *reinterpret_cast<const float2*>(&WN[k * 64 + 2 * l]);
        u64 s0 = pack2(ws.x, ws.x), s1 = pack2(ws.y, ws.y);
        u64 n0 = pack2(wn.x, wn.x), n1 = pack2(wn.y, wn.y);
#pragma unroll
        for (int n = 0; n < 7; n++) {
            u64 xv = xq[n * 64 + k];
            u[n][0] = ffma2(xv, s0, u[n][0]);
            u[n][1] = ffma2(xv, s1, u[n][1]);
            v[n][0] = ffma2(xv, n0, v[n][0]);
            v[n][1] = ffma2(xv, n1, v[n][1]);
        }
    }
    if (SIG) {
#pragma unroll 2
        for (int k = 0; k < 32; k++) {
            float2 ws = *reinterpret_cast<const float2*>(&WS[(64 + k) * 64 + 2 * l]);
            float2 wn = *reinterpret_cast<const float2*>(&WN[(64 + k) * 64 + 2 * l]);
            u64 s0 = pack2(ws.x, ws.x), s1 = pack2(ws.y, ws.y);
            u64 n0 = pack2(wn.x, wn.x), n1 = pack2(wn.y, wn.y);
#pragma unroll
            for (int n = 0; n < 7; n++) {
                u64 xv = sg[n * 32 + k];
                u[n][0] = ffma2(xv, s0, u[n][0]);
                u[n][1] = ffma2(xv, s1, u[n][1]);
                v[n][0] = ffma2(xv, n0, v[n][0]);
                v[n][1] = ffma2(xv, n1, v[n][1]);
            }
        }
    }
}

/* === edge phase (64-wide output): msg=relu(u_i+v_j); max_j(msg@WB)+bb; relu.
   Results overwrite u[][]. mh aliases the x region (old x is dead). === */
__device__ __forceinline__ void edge64(u64* __restrict__ mh,
                                       const float* __restrict__ WB,
                                       const float* __restrict__ BB,
                                       int l, u64 (&u)[7][2], const u64 (&v)[7][2]) {
#pragma unroll
    for (int i = 0; i < 7; i++) {
        __syncwarp();
#pragma unroll
        for (int j = 0; j < 7; j++) {
            if (j == i) continue;
            const int jj = (j < i) ? j : j - 1;
            ulonglong2 mm;
            mm.x = relu2(add2(u[i][0], v[j][0]));
            mm.y = relu2(add2(u[i][1], v[j][1]));
            *reinterpret_cast<ulonglong2*>(&mh[jj * 64 + 2 * l]) = mm;
        }
        __syncwarp();
        u64 a[6][2];
#pragma unroll
        for (int jj = 0; jj < 6; jj++) { a[jj][0] = 0ULL; a[jj][1] = 0ULL; }
#pragma unroll 2
        for (int k = 0; k < 64; k++) {
            float2 wv = *reinterpret_cast<const float2*>(&WB[k * 64 + 2 * l]);
            u64 wx = pack2(wv.x, wv.x), wy = pack2(wv.y, wv.y);
#pragma unroll
            for (int jj = 0; jj < 6; jj++) {
                u64 mv = mh[jj * 64 + k];
                a[jj][0] = ffma2(mv, wx, a[jj][0]);
                a[jj][1] = ffma2(mv, wy, a[jj][1]);
            }
        }
        float2 bb = *reinterpret_cast<const float2*>(&BB[2 * l]);
#pragma unroll
        for (int cc = 0; cc < 2; cc++) {
            float2 m = unpack2(a[0][cc]);
#pragma unroll
            for (int jj = 1; jj < 6; jj++) {
                float2 q = unpack2(a[jj][cc]);
                m.x = fmaxf(m.x, q.x); m.y = fmaxf(m.y, q.y);
            }
            float b = cc ? bb.y : bb.x;
            u[i][cc] = pack2(fmaxf(m.x + b, 0.f), fmaxf(m.y + b, 0.f));
        }
    }
}

/* ================= main fused GNN: one warp per pair of graphs ================= */
__global__ __launch_bounds__(NWARP * 32, 1)
void gnn_main(const float* __restrict__ omega, const float* __restrict__ t,
              const float* __restrict__ wi1, const float* __restrict__ bi1,
              const float* __restrict__ wi2, const float* __restrict__ bi2,
              const float* __restrict__ w1a, const float* __restrict__ b1a,
              const float* __restrict__ w1b, const float* __restrict__ b1b,
              const float* __restrict__ w2a, const float* __restrict__ b2a,
              const float* __restrict__ w2b, const float* __restrict__ b2b,
              const float* __restrict__ w3a, const float* __restrict__ b3a,
              const float* __restrict__ w3b, const float* __restrict__ b3b,
              float* __restrict__ out, int Bn) {
    extern __shared__ float sm[];
    const int tid = threadIdx.x;

    /* ---- load + preprocess weights (EdgeConv split: S = top-bottom, N = bottom) ---- */
    for (int i = tid; i < 4096; i += NWARP * 32) {
        sm[OWI2 + i] = wi2[i];
        sm[OW1B + i] = w1b[i];
        sm[OW2B + i] = w2b[i];
        float bt_ = w1a[4096 + i];
        sm[OW1S + i] = w1a[i] - bt_;
        sm[OW1N + i] = bt_;
    }
    for (int i = tid; i < 6144; i += NWARP * 32) {
        float b2_ = w2a[6144 + i];
        sm[OW2S + i] = w2a[i] - b2_;
        sm[OW2N + i] = b2_;
        float b3_ = w3a[6144 + i];
        sm[OW3S + i] = w3a[i] - b3_;
        sm[OW3N + i] = b3_;
    }
    for (int i = tid; i < 192; i += NWARP * 32) {
        sm[OWI1 + i] = wi1[i];
        sm[OW3B + i] = w3b[i];
    }
    if (tid < 64) {
        sm[OBI1 + tid] = bi1[tid]; sm[OBI2 + tid] = bi2[tid];
        sm[OB1A + tid] = b1a[tid]; sm[OB1B + tid] = b1b[tid];
        sm[OB2A + tid] = b2a[tid]; sm[OB2B + tid] = b2b[tid];
        sm[OB3A + tid] = b3a[tid];
    }
    if (tid < 3) sm[OB3B + tid] = b3b[tid];
    __syncthreads();

    const int w = tid >> 5, l = tid & 31;
    u64* const x64 = reinterpret_cast<u64*>(sm + OACT) + w * WARP_ACT;
    u64* const sg  = x64 + 448;
    u64* const mh  = x64;        /* edge-phase msg buffer aliases old x */
    u64* const sc  = sg;         /* layer-3 reduce scratch aliases sigma */

    const float* WI1f = sm + OWI1; const float* WI2f = sm + OWI2;
    const float* W1Sf = sm + OW1S; const float* W1Nf = sm + OW1N; const float* W1Bf = sm + OW1B;
    const float* W2Sf = sm + OW2S; const float* W2Nf = sm + OW2N; const float* W2Bf = sm + OW2B;
    const float* W3Sf = sm + OW3S; const float* W3Nf = sm + OW3N; const float* W3Bf = sm + OW3B;

    const int npairs = (Bn + 1) >> 1;
    const int jj3 = l / 3, c3 = l - 3 * jj3;

    u64 u[7][2], v[7][2];

    for (int p = blockIdx.x * NWARP + w; p < npairs; p += gridDim.x * NWARP) {
        const int gA = 2 * p;
        const int gB = (2 * p + 1 < Bn) ? (2 * p + 1) : gA;
        __syncwarp();

        /* per-graph 1/(std+1e-7) */
        const float tA = t[gA], tB = t[gB];
        const float invA = 1.f / (sqrtf((expf(2.f * tA * LN_SIGMA) - 1.f) / (2.f * LN_SIGMA)) + 1e-7f);
        const float invB = 1.f / (sqrtf((expf(2.f * tB * LN_SIGMA) - 1.f) / (2.f * LN_SIGMA)) + 1e-7f);

        /* ---- sigma (tile-quirk: xs[node % B]) ---- */
#pragma unroll
        for (int n = 0; n < 7; n++) {
            int nA = gA * 7 + n, nB = gB * 7 + n;
            float sA = g_xs[(size_t)(nA % Bn) * 32 + l];
            float sB = g_xs[(size_t)(nB % Bn) * 32 + l];
            sg[n * 32 + l] = pack2(sA, sB);
        }

        /* ---- init features: hid1 -> x64 scratch; hid2 -> regs -> x64 ---- */
        {
            float2 wd0 = *reinterpret_cast<const float2*>(&WI1f[0 * 64 + 2 * l]);
            float2 wd1 = *reinterpret_cast<const float2*>(&WI1f[1 * 64 + 2 * l]);
            float2 wd2 = *reinterpret_cast<const float2*>(&WI1f[2 * 64 + 2 * l]);
            float2 bb  = *reinterpret_cast<const float2*>(&sm[OBI1 + 2 * l]);
            u64 w0x = pack2(wd0.x, wd0.x), w0y = pack2(wd0.y, wd0.y);
            u64 w1x = pack2(wd1.x, wd1.x), w1y = pack2(wd1.y, wd1.y);
            u64 w2x = pack2(wd2.x, wd2.x), w2y = pack2(wd2.y, wd2.y);
#pragma unroll
            for (int n = 0; n < 7; n++) {
                const float* oA = omega + (size_t)(gA * 7 + n) * 3;
                const float* oB = omega + (size_t)(gB * 7 + n) * 3;
                u64 p0 = pack2(oA[0], oB[0]);
                u64 p1 = pack2(oA[1], oB[1]);
                u64 p2 = pack2(oA[2], oB[2]);
                u64 h0 = pack2(bb.x, bb.x), h1 = pack2(bb.y, bb.y);
                h0 = ffma2(p0, w0x, h0); h0 = ffma2(p1, w1x, h0); h0 = ffma2(p2, w2x, h0);
                h1 = ffma2(p0, w0y, h1); h1 = ffma2(p1, w1y, h1); h1 = ffma2(p2, w2y, h1);
                ulonglong2 hh; hh.x = relu2(h0); hh.y = relu2(h1);
                *reinterpret_cast<ulonglong2*>(&x64[n * 64 + 2 * l]) = hh;
            }
        }
        __syncwarp();
        {
            float2 bi = *reinterpret_cast<const float2*>(&sm[OBI2 + 2 * l]);
#pragma unroll
            for (int n = 0; n < 7; n++) {
                u[n][0] = pack2(bi.x, bi.x); u[n][1] = pack2(bi.y, bi.y);
            }
#pragma unroll 2
            for (int k = 0; k < 64; k++) {
                float2 wv = *reinterpret_cast<const float2*>(&WI2f[k * 64 + 2 * l]);
                u64 wx = pack2(wv.x, wv.x), wy = pack2(wv.y, wv.y);
#pragma unroll
                for (int n = 0; n < 7; n++) {
                    u64 hv = x64[n * 64 + k];
                    u[n][0] = ffma2(hv, wx, u[n][0]);
                    u[n][1] = ffma2(hv, wy, u[n][1]);
                }
            }
        }
        __syncwarp();
#pragma unroll
        for (int n = 0; n < 7; n++) {
            ulonglong2 xx; xx.x = u[n][0]; xx.y = u[n][1];
            *reinterpret_cast<ulonglong2*>(&x64[n * 64 + 2 * l]) = xx;
        }
        __syncwarp();

        /* ---- layer 1 ---- */
        uv_phase<false>(x64, sg, W1Sf, W1Nf, sm + OB1A, l, u, v);
        edge64(mh, W1Bf, sm + OB1B, l, u, v);
        __syncwarp();
#pragma unroll
        for (int n = 0; n < 7; n++) {
            ulonglong2 xx; xx.x = u[n][0]; xx.y = u[n][1];
            *reinterpret_cast<ulonglong2*>(&x64[n * 64 + 2 * l]) = xx;
        }
        __syncwarp();

        /* ---- layer 2 ---- */
        uv_phase<true>(x64, sg, W2Sf, W2Nf, sm + OB2A, l, u, v);
        edge64(mh, W2Bf, sm + OB2B, l, u, v);
        __syncwarp();
#pragma unroll
        for (int n = 0; n < 7; n++) {
            ulonglong2 xx; xx.x = u[n][0]; xx.y = u[n][1];
            *reinterpret_cast<ulonglong2*>(&x64[n * 64 + 2 * l]) = xx;
        }
        __syncwarp();

        /* ---- layer 3 (3-wide output, scaled write) ---- */
        uv_phase<true>(x64, sg, W3Sf, W3Nf, sm + OB3A, l, u, v);
#pragma unroll
        for (int i = 0; i < 7; i++) {
            __syncwarp();
#pragma unroll
            for (int j = 0; j < 7; j++) {
                if (j == i) continue;
                const int jj = (j < i) ? j : j - 1;
                ulonglong2 mm;
                mm.x = relu2(add2(u[i][0], v[j][0]));
                mm.y = relu2(add2(u[i][1], v[j][1]));
                *reinterpret_cast<ulonglong2*>(&mh[jj * 64 + 2 * l]) = mm;
            }
            __syncwarp();
            if (l < 18) {
                u64 acc = 0ULL;
#pragma unroll 4
                for (int k = 0; k < 64; k++) {
                    float wv = W3Bf[k * 3 + c3];
                    acc = ffma2(mh[jj3 * 64 + k], pack2(wv, wv), acc);
                }
                sc[l] = acc;
            }
            __syncwarp();
            if (l < 3) {
                float2 m = unpack2(sc[l]);
#pragma unroll
                for (int jq = 1; jq < 6; jq++) {
                    float2 q = unpack2(sc[jq * 3 + l]);
                    m.x = fmaxf(m.x, q.x); m.y = fmaxf(m.y, q.y);
                }
                float b3 = sm[OB3B + l];
                out[(size_t)(gA * 7 + i) * 3 + l] = (m.x + b3) * invA;
                out[(size_t)(gB * 7 + i) * 3 + l] = (m.y + b3) * invB;
            }
        }
    }
}

extern "C" void kernel_launch(void* const* d_in, const int* in_sizes, int n_in,
                              void* d_out, int out_size) {
    const float* omega = (const float*)d_in[0];
    /* d_in[1] edge_index (fixed all-pairs; computed implicitly), d_in[3] num_objs unused */
    const float* t   = (const float*)d_in[2];
    const float* Wf  = (const float*)d_in[4];
    const float* wi1 = (const float*)d_in[5];  const float* bi1 = (const float*)d_in[6];
    const float* wi2 = (const float*)d_in[7];  const float* bi2 = (const float*)d_in[8];
    const float* wt  = (const float*)d_in[9];  const float* bt  = (const float*)d_in[10];
    const float* w1a = (const float*)d_in[11]; const float* b1a = (const float*)d_in[12];
    const float* w1b = (const float*)d_in[13]; const float* b1b = (const float*)d_in[14];
    const float* w2a = (const float*)d_in[15]; const float* b2a = (const float*)d_in[16];
    const float* w2b = (const float*)d_in[17]; const float* b2b = (const float*)d_in[18];
    const float* w3a = (const float*)d_in[19]; const float* b3a = (const float*)d_in[20];
    const float* w3b = (const float*)d_in[21]; const float* b3b = (const float*)d_in[22];
    float* out = (float*)d_out;

    int Bn = in_sizes[2];
    if (Bn > MAXB) Bn = MAXB;

    xs_kernel<<<(Bn + 255) / 256, 256>>>(t, Wf, wt, bt, Bn);

    cudaFuncSetAttribute(gnn_main, cudaFuncAttributeMaxDynamicSharedMemorySize, SMEM_BYTES);
    int dev = 0, nsm = 148;
    cudaGetDevice(&dev);
    cudaDeviceGetAttribute(&nsm, cudaDevAttrMultiProcessorCount, dev);

    gnn_main<<<nsm, NWARP * 32, SMEM_BYTES>>>(omega, t, wi1, bi1, wi2, bi2,
                                              w1a, b1a, w1b, b1b,
                                              w2a, b2a, w2b, b2b,
                                              w3a, b3a, w3b, b3b, out, Bn);
}